// round 3
// baseline (speedup 1.0000x reference)
#include <cuda_runtime.h>
#include <cuda_bf16.h>
#include <cstdint>

#define B_  8
#define E_  512
#define L_  8192
#define KS  5
#define LC  8188      // L - (KS-1)
#define LD_ 4096      // downsampled length

// ---------------- scratch (device globals; no allocations allowed) ----------
__device__ float          g_y  [(size_t)B_*E_*LC];   // conv output, fp32
__device__ __nv_bfloat16  g_xhi[(size_t)B_*E_*L_];
__device__ __nv_bfloat16  g_xlo[(size_t)B_*E_*L_];
__device__ __nv_bfloat16  g_whi[(size_t)KS*E_*E_];   // [k][o][i]
__device__ __nv_bfloat16  g_wlo[(size_t)KS*E_*E_];
__device__ float          g_s  [(size_t)B_*L_];      // scores, zero beyond LC

// ---------------- conversion kernels ----------------------------------------
__global__ void cvt_x(const float4* __restrict__ x) {
    size_t i = (size_t)blockIdx.x * 256 + threadIdx.x;   // i < B*E*L/4
    float4 v = x[i];
    union { __nv_bfloat16 h[4]; uint2 u; } H, Lo;
    H.h[0] = __float2bfloat16(v.x);
    H.h[1] = __float2bfloat16(v.y);
    H.h[2] = __float2bfloat16(v.z);
    H.h[3] = __float2bfloat16(v.w);
    Lo.h[0] = __float2bfloat16(v.x - __bfloat162float(H.h[0]));
    Lo.h[1] = __float2bfloat16(v.y - __bfloat162float(H.h[1]));
    Lo.h[2] = __float2bfloat16(v.z - __bfloat162float(H.h[2]));
    Lo.h[3] = __float2bfloat16(v.w - __bfloat162float(H.h[3]));
    *reinterpret_cast<uint2*>(&g_xhi[4*i]) = H.u;
    *reinterpret_cast<uint2*>(&g_xlo[4*i]) = Lo.u;
}

__global__ void cvt_w(const float* __restrict__ w) {
    int i = blockIdx.x * 256 + threadIdx.x;
    if (i >= E_*E_*KS) return;
    int k  = i % KS;
    int r  = i / KS;
    int ic = r % E_;
    int oc = r / E_;
    float v = w[i];
    __nv_bfloat16 h = __float2bfloat16(v);
    int dst = (k*E_ + oc)*E_ + ic;
    g_whi[dst] = h;
    g_wlo[dst] = __float2bfloat16(v - __bfloat162float(h));
}

// ---------------- conv implicit GEMM -----------------------------------------
#define BM 128
#define BN 128
#define KC 16
#define SA_STRIDE 24      // bf16 elems per A smem row (conflict-free: 12 banks)
#define SB_STRIDE 18      // bf16 elems per B smem row
#define SA_ELEMS  (KS*BM*SA_STRIDE)          // 15360 per precision
#define SB_ELEMS  (136*SB_STRIDE)            // 2448 per precision
#define SMEM_BYTES ((2*SA_ELEMS + 2*SB_ELEMS) * 2)

__device__ __forceinline__ void mma_bf16(float c[4], const uint32_t a[4], const uint32_t b[2]) {
    asm volatile(
        "mma.sync.aligned.m16n8k16.row.col.f32.bf16.bf16.f32 "
        "{%0,%1,%2,%3}, {%4,%5,%6,%7}, {%8,%9}, {%0,%1,%2,%3};\n"
        : "+f"(c[0]), "+f"(c[1]), "+f"(c[2]), "+f"(c[3])
        : "r"(a[0]), "r"(a[1]), "r"(a[2]), "r"(a[3]), "r"(b[0]), "r"(b[1]));
}

__global__ void __launch_bounds__(256, 1) gemm_conv(const float* __restrict__ conv_b) {
    extern __shared__ __nv_bfloat16 sm[];
    __nv_bfloat16* sAh = sm;
    __nv_bfloat16* sAl = sm + SA_ELEMS;
    __nv_bfloat16* sBh = sm + 2*SA_ELEMS;
    __nv_bfloat16* sBl = sBh + SB_ELEMS;

    const int tid  = threadIdx.x;
    const int warp = tid >> 5, lane = tid & 31;
    const int bb = blockIdx.z;
    const int o0 = blockIdx.y * BM;
    const int t0 = blockIdx.x * BN;
    const int wm = (warp >> 2) * 64;   // 2 warps along M
    const int wn = (warp & 3) * 32;    // 4 warps along N
    const int ar = lane >> 2;          // fragment row within 8
    const int aq = (lane & 3) * 2;     // fragment col pair

    float acc[4][4][4];
    #pragma unroll
    for (int i = 0; i < 4; i++)
        #pragma unroll
        for (int j = 0; j < 4; j++)
            #pragma unroll
            for (int q = 0; q < 4; q++) acc[i][j][q] = 0.f;

    for (int i0 = 0; i0 < E_; i0 += KC) {
        // ---- load A tiles: 5 taps x 128 rows x 16 i's, hi+lo ----
        for (int r = tid; r < KS*BM; r += 256) {
            int k = r / BM, m = r % BM;
            size_t g = (size_t)k*E_*E_ + (size_t)(o0 + m)*E_ + i0;
            uint4 vh0 = *reinterpret_cast<const uint4*>(&g_whi[g]);
            uint4 vh1 = *reinterpret_cast<const uint4*>(&g_whi[g + 8]);
            uint4 vl0 = *reinterpret_cast<const uint4*>(&g_wlo[g]);
            uint4 vl1 = *reinterpret_cast<const uint4*>(&g_wlo[g + 8]);
            *reinterpret_cast<uint4*>(&sAh[r*SA_STRIDE])     = vh0;
            *reinterpret_cast<uint4*>(&sAh[r*SA_STRIDE + 8]) = vh1;
            *reinterpret_cast<uint4*>(&sAl[r*SA_STRIDE])     = vl0;
            *reinterpret_cast<uint4*>(&sAl[r*SA_STRIDE + 8]) = vl1;
        }
        // ---- load B tile transposed: rows t in [0,132), cols i in [0,16) ----
        for (int idx = tid; idx < 16*33; idx += 256) {
            int i  = idx / 33;
            int tq = (idx % 33) * 4;
            size_t g = (size_t)(bb*E_ + i0 + i) * L_ + t0 + tq;
            __nv_bfloat16 hv[4], lv[4];
            if (t0 + tq + 3 < L_) {
                *reinterpret_cast<uint2*>(hv) = *reinterpret_cast<const uint2*>(&g_xhi[g]);
                *reinterpret_cast<uint2*>(lv) = *reinterpret_cast<const uint2*>(&g_xlo[g]);
            } else {
                #pragma unroll
                for (int q = 0; q < 4; q++) {
                    bool ok = (t0 + tq + q) < L_;
                    hv[q] = ok ? g_xhi[g + q] : __float2bfloat16(0.f);
                    lv[q] = ok ? g_xlo[g + q] : __float2bfloat16(0.f);
                }
            }
            #pragma unroll
            for (int q = 0; q < 4; q++) {
                sBh[(tq + q)*SB_STRIDE + i] = hv[q];
                sBl[(tq + q)*SB_STRIDE + i] = lv[q];
            }
        }
        __syncthreads();

        // ---- compute: 5 taps, each is a shifted K=16 GEMM step ----
        #pragma unroll
        for (int k = 0; k < KS; k++) {
            uint32_t Ah[4][4], Al[4][4];
            #pragma unroll
            for (int mf = 0; mf < 4; mf++) {
                int rbase = k*BM + wm + mf*16 + ar;
                const __nv_bfloat16* ph = &sAh[rbase*SA_STRIDE + aq];
                const __nv_bfloat16* pl = &sAl[rbase*SA_STRIDE + aq];
                Ah[mf][0] = *reinterpret_cast<const uint32_t*>(ph);
                Ah[mf][1] = *reinterpret_cast<const uint32_t*>(ph + 8*SA_STRIDE);
                Ah[mf][2] = *reinterpret_cast<const uint32_t*>(ph + 8);
                Ah[mf][3] = *reinterpret_cast<const uint32_t*>(ph + 8*SA_STRIDE + 8);
                Al[mf][0] = *reinterpret_cast<const uint32_t*>(pl);
                Al[mf][1] = *reinterpret_cast<const uint32_t*>(pl + 8*SA_STRIDE);
                Al[mf][2] = *reinterpret_cast<const uint32_t*>(pl + 8);
                Al[mf][3] = *reinterpret_cast<const uint32_t*>(pl + 8*SA_STRIDE + 8);
            }
            uint32_t Bh[4][2], Bl[4][2];
            #pragma unroll
            for (int nf = 0; nf < 4; nf++) {
                int n = wn + nf*8 + ar;
                const __nv_bfloat16* ph = &sBh[(n + k)*SB_STRIDE + aq];
                const __nv_bfloat16* pl = &sBl[(n + k)*SB_STRIDE + aq];
                Bh[nf][0] = *reinterpret_cast<const uint32_t*>(ph);
                Bh[nf][1] = *reinterpret_cast<const uint32_t*>(ph + 8);
                Bl[nf][0] = *reinterpret_cast<const uint32_t*>(pl);
                Bl[nf][1] = *reinterpret_cast<const uint32_t*>(pl + 8);
            }
            #pragma unroll
            for (int mf = 0; mf < 4; mf++)
                #pragma unroll
                for (int nf = 0; nf < 4; nf++) {
                    mma_bf16(acc[mf][nf], Ah[mf], Bh[nf]);
                    mma_bf16(acc[mf][nf], Ah[mf], Bl[nf]);
                    mma_bf16(acc[mf][nf], Al[mf], Bh[nf]);
                }
        }
        __syncthreads();
    }

    // ---- epilogue: add bias, store fp32 y ----
    #pragma unroll
    for (int mf = 0; mf < 4; mf++) {
        int obase = o0 + wm + mf*16 + ar;
        float bv0 = conv_b[obase];
        float bv1 = conv_b[obase + 8];
        #pragma unroll
        for (int nf = 0; nf < 4; nf++) {
            int t = t0 + wn + nf*8 + aq;
            if (t < LC) {
                size_t r0 = (size_t)(bb*E_ + obase)*LC + t;
                float2 v0; v0.x = acc[mf][nf][0] + bv0; v0.y = acc[mf][nf][1] + bv0;
                *reinterpret_cast<float2*>(&g_y[r0]) = v0;
                float2 v1; v1.x = acc[mf][nf][2] + bv1; v1.y = acc[mf][nf][3] + bv1;
                *reinterpret_cast<float2*>(&g_y[r0 + (size_t)8*LC]) = v1;
            }
        }
    }
}

// ---------------- score projection: s[b,t] = sum_e y[b,e,t]*w[e] -------------
__global__ void score_kernel(const float* __restrict__ sw_g) {
    __shared__ float sw[E_];
    for (int i = threadIdx.x; i < E_; i += 256) sw[i] = sw_g[i];
    __syncthreads();
    int b = blockIdx.y;
    int t = blockIdx.x * 256 + threadIdx.x;
    float acc = 0.f;
    if (t < LC) {
        const float* yp = &g_y[(size_t)b*E_*LC + t];
        #pragma unroll 8
        for (int e = 0; e < E_; e++) acc += yp[(size_t)e*LC] * sw[e];
    }
    g_s[(size_t)b*L_ + t] = acc;     // zero for t in [LC, L)
}

// ---------------- GBST combine + downsample ----------------------------------
// block: 512 t positions (256 output td), one b, 32 channels
__global__ void epilogue_kernel(float* __restrict__ out) {
    __shared__ float ss[520];
    __shared__ float att[3][512];
    __shared__ float ys[520];
    const int tid = threadIdx.x;
    const int b  = blockIdx.y;
    const int t0 = blockIdx.x * 512;
    const int eg = blockIdx.z * 32;

    for (int j = tid; j < 516; j += 256) {
        int t = t0 - 2 + j;
        ss[j] = ((unsigned)t < (unsigned)L_) ? g_s[(size_t)b*L_ + t] : 0.f;
    }
    __syncthreads();

    for (int tl = tid; tl < 512; tl += 256) {
        int t = t0 + tl;
        float sc1 = ss[tl + 2];
        int b2 = (t & ~1) - t0;
        float sc2 = 0.5f * (ss[b2 + 2] + ss[b2 + 3]);
        int b3 = (t - (t % 3)) - t0;
        float sc3 = (1.f/3.f) * (ss[b3 + 2] + ss[b3 + 3] + ss[b3 + 4]);
        float m = fmaxf(sc1, fmaxf(sc2, sc3));
        float e1 = __expf(sc1 - m), e2 = __expf(sc2 - m), e3 = __expf(sc3 - m);
        float inv = 1.f / (e1 + e2 + e3);
        att[0][tl] = e1 * inv;
        att[1][tl] = e2 * inv;
        att[2][tl] = e3 * inv;
    }
    __syncthreads();

    const int td = blockIdx.x * 256 + tid;
    for (int ei = 0; ei < 32; ei++) {
        int e = eg + ei;
        const float* yrow = &g_y[(size_t)(b*E_ + e)*LC];
        for (int j = tid; j < 516; j += 256) {
            int t = t0 - 2 + j;
            ys[j] = ((unsigned)t < (unsigned)LC) ? yrow[t] : 0.f;
        }
        __syncthreads();
        float z = 0.f;
        #pragma unroll
        for (int h = 0; h < 2; h++) {
            int t  = 2*td + h;
            int tl = t - t0;
            float s1 = ys[tl + 2];
            int b2 = (t & ~1) - t0;
            float s2 = 0.5f * (ys[b2 + 2] + ys[b2 + 3]);
            int b3 = (t - (t % 3)) - t0;
            float s3 = (1.f/3.f) * (ys[b3 + 2] + ys[b3 + 3] + ys[b3 + 4]);
            z += att[0][tl]*s1 + att[1][tl]*s2 + att[2][tl]*s3;
        }
        out[(size_t)(b*E_ + e)*LD_ + td] = 0.5f * z;
        __syncthreads();
    }
}

// ---------------- launch ------------------------------------------------------
extern "C" void kernel_launch(void* const* d_in, const int* in_sizes, int n_in,
                              void* d_out, int out_size) {
    const float* x       = (const float*)d_in[0];
    const float* conv_w  = (const float*)d_in[1];
    const float* conv_b  = (const float*)d_in[2];
    const float* score_w = (const float*)d_in[3];
    float* out = (float*)d_out;

    cvt_x<<<(B_*E_*L_/4 + 255)/256, 256>>>((const float4*)x);
    cvt_w<<<(E_*E_*KS + 255)/256, 256>>>(conv_w);

    cudaFuncSetAttribute(gemm_conv, cudaFuncAttributeMaxDynamicSharedMemorySize, SMEM_BYTES);
    gemm_conv<<<dim3((LC + BN - 1)/BN, E_/BM, B_), 256, SMEM_BYTES>>>(conv_b);

    score_kernel<<<dim3(L_/256, B_), 256>>>(score_w);
    epilogue_kernel<<<dim3(L_/512, B_, E_/32), 256>>>(out);
}

// round 7
// speedup vs baseline: 2.3502x; 2.3502x over previous
#include <cuda_runtime.h>
#include <cuda_bf16.h>
#include <cstdint>

#define B_  8
#define E_  512
#define L_  8192
#define KS  5
#define LC  8188
#define LD_ 4096

#define BM 128
#define BN 256
#define KC 16
#define A_BYTES 61440              // 2 prec * 5 tap * 128 m * 48B
#define B_BYTES 24960              // 2 prec * 260 t * 48B
#define STAGE   (A_BYTES + B_BYTES)
#define SMEM_TOT (2*STAGE)

// ---------------- scratch ----------------------------------------------------
__device__ __nv_bfloat16 g_xT[((size_t)B_*L_ + 8)*1024];   // [b*L+t][hi512|lo512]
__device__ __nv_bfloat16 g_w2[(size_t)KS*E_*2*E_];         // [k][o][prec][i]
__device__ float g_y[(size_t)B_*E_*LC];
__device__ float g_s[(size_t)B_*L_];

// ---------------- asm helpers ------------------------------------------------
__device__ __forceinline__ uint32_t smem_u32(const void* p) {
    uint32_t a;
    asm("{ .reg .u64 t; cvta.to.shared.u64 t, %1; cvt.u32.u64 %0, t; }" : "=r"(a) : "l"(p));
    return a;
}
__device__ __forceinline__ void cp16(uint32_t dst, const void* src) {
    asm volatile("cp.async.cg.shared.global [%0], [%1], 16;" :: "r"(dst), "l"(src));
}
#define CP_COMMIT() asm volatile("cp.async.commit_group;" ::: "memory")
#define CP_WAIT1()  asm volatile("cp.async.wait_group 1;" ::: "memory")
#define CP_WAIT0()  asm volatile("cp.async.wait_group 0;" ::: "memory")

#define LDSM4(r0, r1, r2, r3, addr) \
    asm volatile("ldmatrix.sync.aligned.m8n8.x4.shared.b16 {%0,%1,%2,%3}, [%4];" \
        : "=r"(r0), "=r"(r1), "=r"(r2), "=r"(r3) : "r"(addr))

__device__ __forceinline__ void mma_bf16(float c[4], const uint32_t a[4],
                                         uint32_t b0, uint32_t b1) {
    asm volatile(
        "mma.sync.aligned.m16n8k16.row.col.f32.bf16.bf16.f32 "
        "{%0,%1,%2,%3}, {%4,%5,%6,%7}, {%8,%9}, {%0,%1,%2,%3};\n"
        : "+f"(c[0]), "+f"(c[1]), "+f"(c[2]), "+f"(c[3])
        : "r"(a[0]), "r"(a[1]), "r"(a[2]), "r"(a[3]), "r"(b0), "r"(b1));
}

// ---------------- setup kernels ----------------------------------------------
__global__ void zero_s() {
    g_s[blockIdx.x * 1024 + threadIdx.x] = 0.f;
}

__global__ void cvt_x(const float* __restrict__ x) {
    __shared__ float tile[32][33];
    const int b = blockIdx.z, e0 = blockIdx.y * 32, t0 = blockIdx.x * 32;
    const int tx = threadIdx.x & 31, ty = threadIdx.x >> 5;
    #pragma unroll
    for (int r = 0; r < 4; r++)
        tile[ty + 8*r][tx] = x[((size_t)b*E_ + e0 + ty + 8*r)*L_ + t0 + tx];
    __syncthreads();
    #pragma unroll
    for (int r = 0; r < 4; r++) {
        int tl = ty + 8*r;
        float v = tile[tx][tl];
        __nv_bfloat16 h = __float2bfloat16(v);
        size_t row = ((size_t)b*L_ + t0 + tl)*1024;
        g_xT[row + e0 + tx] = h;
        g_xT[row + 512 + e0 + tx] = __float2bfloat16(v - __bfloat162float(h));
    }
}

__global__ void cvt_w(const float* __restrict__ w) {
    int i = blockIdx.x * 256 + threadIdx.x;
    if (i >= E_*E_*KS) return;
    int k = i % KS;
    int r = i / KS;
    int ii = r % E_, o = r / E_;
    float v = w[i];
    __nv_bfloat16 h = __float2bfloat16(v);
    size_t base = ((size_t)(k*E_ + o)*2)*E_ + ii;
    g_w2[base] = h;                                   // prec 0 (hi)
    g_w2[base + E_] = __float2bfloat16(v - __bfloat162float(h));  // prec 1 (lo)
}

// ---------------- main GEMM (conv as 5 shifted GEMMs) + fused score ----------
__global__ void __launch_bounds__(256, 1) gemm_conv(
    const float* __restrict__ conv_b, const float* __restrict__ score_w)
{
    extern __shared__ char smem[];
    const uint32_t su = smem_u32(smem);
    const int tid = threadIdx.x, warp = tid >> 5, lane = tid & 31;
    const int b = blockIdx.z, o0 = blockIdx.y * BM, t0 = blockIdx.x * BN;
    const int wm = (warp >> 2) * 64, wn = (warp & 3) * 64;
    const __nv_bfloat16* gx = g_xT + ((size_t)b*L_ + t0)*1024;

    float acc[4][8][4];
    #pragma unroll
    for (int mf = 0; mf < 4; mf++)
        #pragma unroll
        for (int nf = 0; nf < 8; nf++)
            #pragma unroll
            for (int q = 0; q < 4; q++) acc[mf][nf][q] = 0.f;

    // lane-dependent ldmatrix bases (A: rows m, 48B stride; B: rows t, 48B stride)
    const uint32_t aL = (uint32_t)((wm + (lane & 7) + ((lane >> 3) & 1)*8)*48
                                   + ((lane >> 4) & 1)*16);
    const uint32_t bL = (uint32_t)(A_BYTES + (wn + (lane & 7) + ((lane >> 4) & 1)*8)*48
                                   + ((lane >> 3) & 1)*16);

    // ---- stage loader: i-chunk s -> buffer s&1 ----
    auto load_stage = [&](int s) {
        const uint32_t dst0 = su + (uint32_t)(s & 1)*STAGE;
        const int i0 = s * KC;
        // A: 2 prec x 5 tap x 128 m rows of 32B
        for (int r = tid; r < 1280; r += 256) {
            int prec = (r >= 640);
            int rr = prec ? r - 640 : r;
            int tap = rr >> 7, m = rr & 127;
            const __nv_bfloat16* src =
                g_w2 + ((size_t)((tap*E_ + o0 + m)*2 + prec))*E_ + i0;
            uint32_t d = dst0 + (uint32_t)(prec*30720 + rr*48);
            cp16(d, src); cp16(d + 16, src + 8);
        }
        // B: 2 prec x 260 t rows of 32B
        for (int r = tid; r < 520; r += 256) {
            int prec = (r >= 260);
            int t = prec ? r - 260 : r;
            const __nv_bfloat16* src = gx + (size_t)t*1024 + prec*512 + i0;
            uint32_t d = dst0 + (uint32_t)(A_BYTES + prec*12480 + t*48);
            cp16(d, src); cp16(d + 16, src + 8);
        }
    };

    load_stage(0); CP_COMMIT();

    for (int s = 0; s < E_/KC; s++) {
        if (s + 1 < E_/KC) { load_stage(s + 1); CP_COMMIT(); CP_WAIT1(); }
        else               { CP_WAIT0(); }
        __syncthreads();

        const uint32_t sbase = su + (uint32_t)(s & 1)*STAGE;
        #pragma unroll
        for (int tap = 0; tap < KS; tap++) {
            // B fragments, both precisions: 16 n x 16 k per LDSM
            uint32_t bfr[2][4][4];
            #pragma unroll
            for (int prec = 0; prec < 2; prec++)
                #pragma unroll
                for (int nfp = 0; nfp < 4; nfp++)
                    LDSM4(bfr[prec][nfp][0], bfr[prec][nfp][1],
                          bfr[prec][nfp][2], bfr[prec][nfp][3],
                          sbase + bL + (uint32_t)(prec*12480 + tap*48 + nfp*768));
            uint32_t a[4][4];
            // pass 1: A-hi -> hi*hi and hi*lo
            #pragma unroll
            for (int mf = 0; mf < 4; mf++)
                LDSM4(a[mf][0], a[mf][1], a[mf][2], a[mf][3],
                      sbase + aL + (uint32_t)(tap*6144 + mf*768));
            #pragma unroll
            for (int mf = 0; mf < 4; mf++)
                #pragma unroll
                for (int nf = 0; nf < 8; nf++) {
                    int nfp = nf >> 1, q = (nf & 1)*2;
                    mma_bf16(acc[mf][nf], a[mf], bfr[0][nfp][q], bfr[0][nfp][q+1]);
                    mma_bf16(acc[mf][nf], a[mf], bfr[1][nfp][q], bfr[1][nfp][q+1]);
                }
            // pass 2: A-lo -> lo*hi
            #pragma unroll
            for (int mf = 0; mf < 4; mf++)
                LDSM4(a[mf][0], a[mf][1], a[mf][2], a[mf][3],
                      sbase + aL + (uint32_t)(30720 + tap*6144 + mf*768));
            #pragma unroll
            for (int mf = 0; mf < 4; mf++)
                #pragma unroll
                for (int nf = 0; nf < 8; nf++) {
                    int nfp = nf >> 1, q = (nf & 1)*2;
                    mma_bf16(acc[mf][nf], a[mf], bfr[0][nfp][q], bfr[0][nfp][q+1]);
                }
        }
        __syncthreads();
    }

    // ---- epilogue: bias, store y, fused score reduction ----
    const int ar = lane >> 2, aq = (lane & 3)*2;
    float bvv[4][2], wsv[4][2];
    #pragma unroll
    for (int mf = 0; mf < 4; mf++) {
        int o = o0 + wm + mf*16 + ar;
        bvv[mf][0] = conv_b[o];     bvv[mf][1] = conv_b[o + 8];
        wsv[mf][0] = score_w[o];    wsv[mf][1] = score_w[o + 8];
    }
    #pragma unroll
    for (int mf = 0; mf < 4; mf++) {
        int o = o0 + wm + mf*16 + ar;
        #pragma unroll
        for (int nf = 0; nf < 8; nf++) {
            int t = t0 + wn + nf*8 + aq;
            float y0 = acc[mf][nf][0] + bvv[mf][0];
            float y1 = acc[mf][nf][1] + bvv[mf][0];
            float y2 = acc[mf][nf][2] + bvv[mf][1];
            float y3 = acc[mf][nf][3] + bvv[mf][1];
            size_t r0 = ((size_t)(b*E_ + o))*LC + t;
            size_t r1 = r0 + (size_t)8*LC;
            if (t + 1 < LC) {
                *reinterpret_cast<float2*>(&g_y[r0]) = make_float2(y0, y1);
                *reinterpret_cast<float2*>(&g_y[r1]) = make_float2(y2, y3);
            } else if (t < LC) {
                g_y[r0] = y0; g_y[r1] = y2;
            }
        }
    }
    #pragma unroll
    for (int nf = 0; nf < 8; nf++) {
        float s0 = 0.f, s1 = 0.f;
        #pragma unroll
        for (int mf = 0; mf < 4; mf++) {
            s0 += wsv[mf][0]*(acc[mf][nf][0] + bvv[mf][0])
                + wsv[mf][1]*(acc[mf][nf][2] + bvv[mf][1]);
            s1 += wsv[mf][0]*(acc[mf][nf][1] + bvv[mf][0])
                + wsv[mf][1]*(acc[mf][nf][3] + bvv[mf][1]);
        }
        #pragma unroll
        for (int d = 4; d <= 16; d <<= 1) {
            s0 += __shfl_xor_sync(0xFFFFFFFFu, s0, d);
            s1 += __shfl_xor_sync(0xFFFFFFFFu, s1, d);
        }
        if (lane < 4) {
            int t = t0 + wn + nf*8 + aq;
            if (t < LC)     atomicAdd(&g_s[(size_t)b*L_ + t],     s0);
            if (t + 1 < LC) atomicAdd(&g_s[(size_t)b*L_ + t + 1], s1);
        }
    }
}

// ---------------- GBST combine + downsample (proven in R1) -------------------
__global__ void epilogue_kernel(float* __restrict__ out) {
    __shared__ float ss[520];
    __shared__ float att[3][512];
    __shared__ float ys[520];
    const int tid = threadIdx.x;
    const int b  = blockIdx.y;
    const int t0 = blockIdx.x * 512;
    const int eg = blockIdx.z * 32;

    for (int j = tid; j < 516; j += 256) {
        int t = t0 - 2 + j;
        ss[j] = ((unsigned)t < (unsigned)L_) ? g_s[(size_t)b*L_ + t] : 0.f;
    }
    __syncthreads();
    for (int tl = tid; tl < 512; tl += 256) {
        int t = t0 + tl;
        float sc1 = ss[tl + 2];
        int b2 = (t & ~1) - t0;
        float sc2 = 0.5f * (ss[b2 + 2] + ss[b2 + 3]);
        int b3 = (t - (t % 3)) - t0;
        float sc3 = (1.f/3.f) * (ss[b3 + 2] + ss[b3 + 3] + ss[b3 + 4]);
        float m = fmaxf(sc1, fmaxf(sc2, sc3));
        float e1 = __expf(sc1 - m), e2 = __expf(sc2 - m), e3 = __expf(sc3 - m);
        float inv = 1.f / (e1 + e2 + e3);
        att[0][tl] = e1 * inv; att[1][tl] = e2 * inv; att[2][tl] = e3 * inv;
    }
    __syncthreads();
    const int td = blockIdx.x * 256 + tid;
    for (int ei = 0; ei < 32; ei++) {
        int e = eg + ei;
        const float* yrow = &g_y[(size_t)(b*E_ + e)*LC];
        for (int j = tid; j < 516; j += 256) {
            int t = t0 - 2 + j;
            ys[j] = ((unsigned)t < (unsigned)LC) ? yrow[t] : 0.f;
        }
        __syncthreads();
        float z = 0.f;
        #pragma unroll
        for (int h = 0; h < 2; h++) {
            int t  = 2*td + h;
            int tl = t - t0;
            float s1 = ys[tl + 2];
            int b2 = (t & ~1) - t0;
            float s2 = 0.5f * (ys[b2 + 2] + ys[b2 + 3]);
            int b3 = (t - (t % 3)) - t0;
            float s3 = (1.f/3.f) * (ys[b3 + 2] + ys[b3 + 3] + ys[b3 + 4]);
            z += att[0][tl]*s1 + att[1][tl]*s2 + att[2][tl]*s3;
        }
        out[(size_t)(b*E_ + e)*LD_ + td] = 0.5f * z;
        __syncthreads();
    }
}

// ---------------- launch ------------------------------------------------------
extern "C" void kernel_launch(void* const* d_in, const int* in_sizes, int n_in,
                              void* d_out, int out_size) {
    const float* x       = (const float*)d_in[0];
    const float* conv_w  = (const float*)d_in[1];
    const float* conv_b  = (const float*)d_in[2];
    const float* score_w = (const float*)d_in[3];
    float* out = (float*)d_out;

    zero_s<<<B_*L_/1024, 1024>>>();
    cvt_x<<<dim3(L_/32, E_/32, B_), 256>>>(x);
    cvt_w<<<(E_*E_*KS + 255)/256, 256>>>(conv_w);

    cudaFuncSetAttribute(gemm_conv, cudaFuncAttributeMaxDynamicSharedMemorySize, SMEM_TOT);
    gemm_conv<<<dim3(L_/BN, E_/BM, B_), 256, SMEM_TOT>>>(conv_b, score_w);

    epilogue_kernel<<<dim3(L_/512, B_, E_/32), 256>>>(out);
}

// round 8
// speedup vs baseline: 3.9275x; 1.6711x over previous
#include <cuda_runtime.h>
#include <cuda_fp16.h>
#include <cstdint>

#define B_  8
#define E_  512
#define L_  8192
#define KS  5
#define LC  8188
#define LD_ 4096

#define BM 128
#define BN 256
#define KC 32
#define NSTAGES (E_/KC)            // 16
#define A_BYTES 51200              // 5 tap * 128 m * 80B
#define B_BYTES 41600              // 2 prec * 260 t * 80B
#define STAGE   (A_BYTES + B_BYTES)   // 92800
#define SMEM_TOT (2*STAGE)            // 185600

// ---------------- scratch ----------------------------------------------------
__device__ __half g_xT[((size_t)B_*L_ + 8)*1024];   // [b*L+t][hi512|lo512]
__device__ __half g_w1[(size_t)KS*E_*E_];           // [tap][o][i], single fp16
__device__ float g_y[(size_t)B_*E_*LC];
__device__ float g_s[(size_t)B_*L_];

// ---------------- asm helpers ------------------------------------------------
__device__ __forceinline__ uint32_t smem_u32(const void* p) {
    uint32_t a;
    asm("{ .reg .u64 t; cvta.to.shared.u64 t, %1; cvt.u32.u64 %0, t; }" : "=r"(a) : "l"(p));
    return a;
}
__device__ __forceinline__ void cp16(uint32_t dst, const void* src) {
    asm volatile("cp.async.cg.shared.global [%0], [%1], 16;" :: "r"(dst), "l"(src));
}
#define CP_COMMIT() asm volatile("cp.async.commit_group;" ::: "memory")
#define CP_WAIT1()  asm volatile("cp.async.wait_group 1;" ::: "memory")
#define CP_WAIT0()  asm volatile("cp.async.wait_group 0;" ::: "memory")

#define LDSM4(r0, r1, r2, r3, addr) \
    asm volatile("ldmatrix.sync.aligned.m8n8.x4.shared.b16 {%0,%1,%2,%3}, [%4];" \
        : "=r"(r0), "=r"(r1), "=r"(r2), "=r"(r3) : "r"(addr))

__device__ __forceinline__ void mma_f16(float c[4], const uint32_t a[4],
                                        uint32_t b0, uint32_t b1) {
    asm volatile(
        "mma.sync.aligned.m16n8k16.row.col.f32.f16.f16.f32 "
        "{%0,%1,%2,%3}, {%4,%5,%6,%7}, {%8,%9}, {%0,%1,%2,%3};\n"
        : "+f"(c[0]), "+f"(c[1]), "+f"(c[2]), "+f"(c[3])
        : "r"(a[0]), "r"(a[1]), "r"(a[2]), "r"(a[3]), "r"(b0), "r"(b1));
}

// ---------------- setup kernels ----------------------------------------------
__global__ void zero_s() {
    g_s[blockIdx.x * 1024 + threadIdx.x] = 0.f;
}

__global__ void cvt_x(const float* __restrict__ x) {
    __shared__ float tile[32][33];
    const int b = blockIdx.z, e0 = blockIdx.y * 32, t0 = blockIdx.x * 32;
    const int tx = threadIdx.x & 31, ty = threadIdx.x >> 5;
    #pragma unroll
    for (int r = 0; r < 4; r++)
        tile[ty + 8*r][tx] = x[((size_t)b*E_ + e0 + ty + 8*r)*L_ + t0 + tx];
    __syncthreads();
    #pragma unroll
    for (int r = 0; r < 4; r++) {
        int tl = ty + 8*r;
        float v = tile[tx][tl];
        __half h = __float2half(v);
        size_t row = ((size_t)b*L_ + t0 + tl)*1024;
        g_xT[row + e0 + tx] = h;
        g_xT[row + 512 + e0 + tx] = __float2half(v - __half2float(h));
    }
}

__global__ void cvt_w(const float* __restrict__ w) {
    int i = blockIdx.x * 256 + threadIdx.x;
    if (i >= E_*E_*KS) return;
    int k = i % KS;
    int r = i / KS;
    int ii = r % E_, o = r / E_;
    g_w1[((size_t)k*E_ + o)*E_ + ii] = __float2half(w[i]);
}

// ---------------- main GEMM (conv as 5 shifted GEMMs) + fused score ----------
__global__ void __launch_bounds__(256, 1) gemm_conv(
    const float* __restrict__ conv_b, const float* __restrict__ score_w)
{
    extern __shared__ char smem[];
    const uint32_t su = smem_u32(smem);
    const int tid = threadIdx.x, warp = tid >> 5, lane = tid & 31;
    const int b = blockIdx.z, o0 = blockIdx.y * BM, t0 = blockIdx.x * BN;
    const int wm = (warp >> 2) * 64, wn = (warp & 3) * 64;
    const __half* gx = g_xT + ((size_t)b*L_ + t0)*1024;

    float acc[4][8][4];
    #pragma unroll
    for (int mf = 0; mf < 4; mf++)
        #pragma unroll
        for (int nf = 0; nf < 8; nf++)
            #pragma unroll
            for (int q = 0; q < 4; q++) acc[mf][nf][q] = 0.f;

    // lane-dependent ldmatrix bases (row stride 80B)
    const uint32_t aL = (uint32_t)((wm + (lane & 7) + ((lane >> 3) & 1)*8)*80
                                   + ((lane >> 4) & 1)*16);
    const uint32_t bL = (uint32_t)(A_BYTES + (wn + (lane & 7) + ((lane >> 4) & 1)*8)*80
                                   + ((lane >> 3) & 1)*16);

    // ---- stage loader: i-chunk s (KC=32) -> buffer s&1 ----
    auto load_stage = [&](int s) {
        const uint32_t dst0 = su + (uint32_t)(s & 1)*STAGE;
        const int i0 = s * KC;
        // A: 5 tap x 128 m rows x 64B  (2560 16B-chunks)
        #pragma unroll
        for (int it = 0; it < 10; it++) {
            int idx = tid + it*256;
            int row = idx >> 2, part = idx & 3;
            int tap = row >> 7, m = row & 127;
            const __half* src = g_w1 + ((size_t)tap*E_ + o0 + m)*E_ + i0 + part*8;
            cp16(dst0 + (uint32_t)(row*80 + part*16), src);
        }
        // B: 2 prec x 260 t rows x 64B  (2080 16B-chunks)
        for (int idx = tid; idx < 2080; idx += 256) {
            int row = idx >> 2, part = idx & 3;
            int prec = row >= 260;
            int t = row - (prec ? 260 : 0);
            const __half* src = gx + (size_t)t*1024 + prec*512 + i0 + part*8;
            cp16(dst0 + (uint32_t)(A_BYTES + row*80 + part*16), src);
        }
    };

    load_stage(0); CP_COMMIT();

    for (int s = 0; s < NSTAGES; s++) {
        if (s + 1 < NSTAGES) { load_stage(s + 1); CP_COMMIT(); CP_WAIT1(); }
        else                 { CP_WAIT0(); }
        __syncthreads();

        const uint32_t sbase = su + (uint32_t)(s & 1)*STAGE;
        #pragma unroll
        for (int tap = 0; tap < KS; tap++) {
            #pragma unroll
            for (int kc = 0; kc < 2; kc++) {
                uint32_t bfr[2][4][4];
                #pragma unroll
                for (int prec = 0; prec < 2; prec++)
                    #pragma unroll
                    for (int nfp = 0; nfp < 4; nfp++)
                        LDSM4(bfr[prec][nfp][0], bfr[prec][nfp][1],
                              bfr[prec][nfp][2], bfr[prec][nfp][3],
                              sbase + bL + (uint32_t)(prec*20800 + tap*80
                                                      + nfp*1280 + kc*32));
                uint32_t a[4][4];
                #pragma unroll
                for (int mf = 0; mf < 4; mf++)
                    LDSM4(a[mf][0], a[mf][1], a[mf][2], a[mf][3],
                          sbase + aL + (uint32_t)(tap*10240 + mf*1280 + kc*32));
                #pragma unroll
                for (int mf = 0; mf < 4; mf++)
                    #pragma unroll
                    for (int nf = 0; nf < 8; nf++) {
                        int nfp = nf >> 1, q = (nf & 1)*2;
                        mma_f16(acc[mf][nf], a[mf], bfr[0][nfp][q], bfr[0][nfp][q+1]);
                        mma_f16(acc[mf][nf], a[mf], bfr[1][nfp][q], bfr[1][nfp][q+1]);
                    }
            }
        }
        __syncthreads();
    }

    // ---- epilogue: bias, store y, fused score reduction ----
    const int ar = lane >> 2, aq = (lane & 3)*2;
    float bvv[4][2], wsv[4][2];
    #pragma unroll
    for (int mf = 0; mf < 4; mf++) {
        int o = o0 + wm + mf*16 + ar;
        bvv[mf][0] = conv_b[o];     bvv[mf][1] = conv_b[o + 8];
        wsv[mf][0] = score_w[o];    wsv[mf][1] = score_w[o + 8];
    }
    #pragma unroll
    for (int mf = 0; mf < 4; mf++) {
        int o = o0 + wm + mf*16 + ar;
        #pragma unroll
        for (int nf = 0; nf < 8; nf++) {
            int t = t0 + wn + nf*8 + aq;
            float y0 = acc[mf][nf][0] + bvv[mf][0];
            float y1 = acc[mf][nf][1] + bvv[mf][0];
            float y2 = acc[mf][nf][2] + bvv[mf][1];
            float y3 = acc[mf][nf][3] + bvv[mf][1];
            size_t r0 = ((size_t)(b*E_ + o))*LC + t;
            size_t r1 = r0 + (size_t)8*LC;
            if (t + 1 < LC) {
                *reinterpret_cast<float2*>(&g_y[r0]) = make_float2(y0, y1);
                *reinterpret_cast<float2*>(&g_y[r1]) = make_float2(y2, y3);
            } else if (t < LC) {
                g_y[r0] = y0; g_y[r1] = y2;
            }
        }
    }
    #pragma unroll
    for (int nf = 0; nf < 8; nf++) {
        float s0 = 0.f, s1 = 0.f;
        #pragma unroll
        for (int mf = 0; mf < 4; mf++) {
            s0 += wsv[mf][0]*(acc[mf][nf][0] + bvv[mf][0])
                + wsv[mf][1]*(acc[mf][nf][2] + bvv[mf][1]);
            s1 += wsv[mf][0]*(acc[mf][nf][1] + bvv[mf][0])
                + wsv[mf][1]*(acc[mf][nf][3] + bvv[mf][1]);
        }
        #pragma unroll
        for (int d = 4; d <= 16; d <<= 1) {
            s0 += __shfl_xor_sync(0xFFFFFFFFu, s0, d);
            s1 += __shfl_xor_sync(0xFFFFFFFFu, s1, d);
        }
        if (lane < 4) {
            int t = t0 + wn + nf*8 + aq;
            if (t < LC)     atomicAdd(&g_s[(size_t)b*L_ + t],     s0);
            if (t + 1 < LC) atomicAdd(&g_s[(size_t)b*L_ + t + 1], s1);
        }
    }
}

// ---------------- GBST combine + downsample ----------------------------------
__global__ void epilogue_kernel(float* __restrict__ out) {
    __shared__ float ss[520];
    __shared__ float att[3][512];
    __shared__ float ys[520];
    const int tid = threadIdx.x;
    const int b  = blockIdx.y;
    const int t0 = blockIdx.x * 512;
    const int eg = blockIdx.z * 32;

    for (int j = tid; j < 516; j += 256) {
        int t = t0 - 2 + j;
        ss[j] = ((unsigned)t < (unsigned)L_) ? g_s[(size_t)b*L_ + t] : 0.f;
    }
    __syncthreads();
    for (int tl = tid; tl < 512; tl += 256) {
        int t = t0 + tl;
        float sc1 = ss[tl + 2];
        int b2 = (t & ~1) - t0;
        float sc2 = 0.5f * (ss[b2 + 2] + ss[b2 + 3]);
        int b3 = (t - (t % 3)) - t0;
        float sc3 = (1.f/3.f) * (ss[b3 + 2] + ss[b3 + 3] + ss[b3 + 4]);
        float m = fmaxf(sc1, fmaxf(sc2, sc3));
        float e1 = __expf(sc1 - m), e2 = __expf(sc2 - m), e3 = __expf(sc3 - m);
        float inv = 1.f / (e1 + e2 + e3);
        att[0][tl] = e1 * inv; att[1][tl] = e2 * inv; att[2][tl] = e3 * inv;
    }
    __syncthreads();
    const int td = blockIdx.x * 256 + tid;
    for (int ei = 0; ei < 32; ei++) {
        int e = eg + ei;
        const float* yrow = &g_y[(size_t)(b*E_ + e)*LC];
        for (int j = tid; j < 516; j += 256) {
            int t = t0 - 2 + j;
            ys[j] = ((unsigned)t < (unsigned)LC) ? yrow[t] : 0.f;
        }
        __syncthreads();
        float z = 0.f;
        #pragma unroll
        for (int h = 0; h < 2; h++) {
            int t  = 2*td + h;
            int tl = t - t0;
            float s1 = ys[tl + 2];
            int b2 = (t & ~1) - t0;
            float s2 = 0.5f * (ys[b2 + 2] + ys[b2 + 3]);
            int b3 = (t - (t % 3)) - t0;
            float s3 = (1.f/3.f) * (ys[b3 + 2] + ys[b3 + 3] + ys[b3 + 4]);
            z += att[0][tl]*s1 + att[1][tl]*s2 + att[2][tl]*s3;
        }
        out[(size_t)(b*E_ + e)*LD_ + td] = 0.5f * z;
        __syncthreads();
    }
}

// ---------------- launch ------------------------------------------------------
extern "C" void kernel_launch(void* const* d_in, const int* in_sizes, int n_in,
                              void* d_out, int out_size) {
    const float* x       = (const float*)d_in[0];
    const float* conv_w  = (const float*)d_in[1];
    const float* conv_b  = (const float*)d_in[2];
    const float* score_w = (const float*)d_in[3];
    float* out = (float*)d_out;

    zero_s<<<B_*L_/1024, 1024>>>();
    cvt_x<<<dim3(L_/32, E_/32, B_), 256>>>(x);
    cvt_w<<<(E_*E_*KS + 255)/256, 256>>>(conv_w);

    cudaFuncSetAttribute(gemm_conv, cudaFuncAttributeMaxDynamicSharedMemorySize, SMEM_TOT);
    gemm_conv<<<dim3(L_/BN, E_/BM, B_), 256, SMEM_TOT>>>(conv_b, score_w);

    epilogue_kernel<<<dim3(L_/512, B_, E_/32), 256>>>(out);
}